// round 11
// baseline (speedup 1.0000x reference)
#include <cuda_runtime.h>

// ---------------------------------------------------------------------------
// Problem constants
// ---------------------------------------------------------------------------
namespace {
constexpr int kB  = 8;
constexpr int kN  = 512;
constexpr int kS  = 96;
constexpr int kH  = 256;
constexpr int kNH = 8;
constexpr int kHD = 32;
constexpr int kOUT = 4;
constexpr int MQ = kB * kN;   // 4096 query rows
constexpr int MT = kB * kS;   // 768 temporal rows
}

// ---------------------------------------------------------------------------
// Scratch (device globals — no allocation allowed)
// ---------------------------------------------------------------------------
__device__ __align__(16) float g_Wqs[kH * kH];        // Wq @ Ws
__device__ __align__(16) float g_Wkvt[2 * kH * kH];   // [Wk;Wv] @ Wt
__device__ __align__(16) float g_W1ao[kH * kH];       // W1 @ Wao
__device__ __align__(16) float g_bqs[kH];
__device__ __align__(16) float g_bkvt[2 * kH];
__device__ __align__(16) float g_b1ao[kH];
__device__ __align__(16) float g_q[MQ * kH];
__device__ __align__(16) float g_kv[MT * 2 * kH];     // [..,0:256]=k, [..,256:512]=v
__device__ __align__(16) float g_ctx[MQ * kH];
__device__ __align__(16) float g_fused[MQ * kH];

// ---------------------------------------------------------------------------
// f32x2 packed-math helpers (sm_103a fma.rn.f32x2 — PTX only)
// ---------------------------------------------------------------------------
using u64 = unsigned long long;
__device__ __forceinline__ u64 pack2(float lo, float hi) {
    u64 r; asm("mov.b64 %0, {%1, %2};" : "=l"(r) : "f"(lo), "f"(hi)); return r;
}
__device__ __forceinline__ u64 dup2(float x) {
    u64 r; asm("mov.b64 %0, {%1, %1};" : "=l"(r) : "f"(x)); return r;
}
__device__ __forceinline__ void ffma2(u64& d, u64 a, u64 b) {
    asm("fma.rn.f32x2 %0, %1, %2, %0;" : "+l"(d) : "l"(a), "l"(b));
}
__device__ __forceinline__ void fmul2(u64& d, u64 a) {
    asm("mul.rn.f32x2 %0, %0, %1;" : "+l"(d) : "l"(a));
}
__device__ __forceinline__ float2 unpk(u64 v) {
    float2 f; asm("mov.b64 {%0, %1}, %2;" : "=f"(f.x), "=f"(f.y) : "l"(v)); return f;
}

// ---------------------------------------------------------------------------
// f32x2 SGEMM body: C[M,N] = A[M,K] @ op(B) + bias, optional ReLU
//   BT = true :  op(B) = B^T, B row-major [N,K]   (NT)
//   BT = false:  op(B) = B,   B row-major [K,N]   (NN)
// 32x64 block tile, BK=16, 128 threads, 4x4 per thread (2 row-pairs x 4 cols),
// double-buffered smem; B stored duplicated as (b,b) u64 so FFMA2 operands
// need no per-iteration packing. A pairs come free from ulonglong2 reads.
// Requires M%32==0, N%64==0, K%16==0, K>=32.
// ---------------------------------------------------------------------------
template <bool BT, bool RELU>
__device__ __forceinline__ void gemm_body(
    const float* __restrict__ A, const float* __restrict__ Bm,
    const float* __restrict__ bias, float* __restrict__ C,
    int M, int N, int K, int bx, int by)
{
    __shared__ __align__(16) float As[2][16][32];
    __shared__ __align__(16) u64   Bs[2][16][64];

    const int tid = threadIdx.x;       // 0..127
    const int tx  = tid & 15;          // col group: cols n0 + tx*4 .. +3
    const int ty  = tid >> 4;          // row group: rows m0 + ty*4 .. +3
    const int m0  = by * 32;
    const int n0  = bx * 64;

    // loader mapping
    const int lr = tid & 31;           // 0..31
    const int lk = (tid >> 5) << 2;    // 0,4,8,12
    const int knn = tid >> 4;          // 0..7 (NN)

    const float* Aptr = A + (m0 + lr) * K + lk;
    const float* Bptr = BT ? (Bm + (n0 + lr) * K + lk)
                           : (Bm + knn * N + n0 + (tx << 2));

    float4 aR  = *(const float4*)Aptr;
    float4 b0R = *(const float4*)Bptr;
    float4 b1R = BT ? *(const float4*)(Bptr + 32 * K)
                    : *(const float4*)(Bptr + 8 * N);

    u64 acc[2][4];
#pragma unroll
    for (int p = 0; p < 2; p++)
#pragma unroll
        for (int j = 0; j < 4; j++) acc[p][j] = 0ull;

    // stage 0 store
    {
        As[0][lk + 0][lr] = aR.x;
        As[0][lk + 1][lr] = aR.y;
        As[0][lk + 2][lr] = aR.z;
        As[0][lk + 3][lr] = aR.w;
        if (BT) {
            Bs[0][lk + 0][lr] = dup2(b0R.x);
            Bs[0][lk + 1][lr] = dup2(b0R.y);
            Bs[0][lk + 2][lr] = dup2(b0R.z);
            Bs[0][lk + 3][lr] = dup2(b0R.w);
            Bs[0][lk + 0][lr + 32] = dup2(b1R.x);
            Bs[0][lk + 1][lr + 32] = dup2(b1R.y);
            Bs[0][lk + 2][lr + 32] = dup2(b1R.z);
            Bs[0][lk + 3][lr + 32] = dup2(b1R.w);
        } else {
            Bs[0][knn][(tx << 2) + 0] = dup2(b0R.x);
            Bs[0][knn][(tx << 2) + 1] = dup2(b0R.y);
            Bs[0][knn][(tx << 2) + 2] = dup2(b0R.z);
            Bs[0][knn][(tx << 2) + 3] = dup2(b0R.w);
            Bs[0][knn + 8][(tx << 2) + 0] = dup2(b1R.x);
            Bs[0][knn + 8][(tx << 2) + 1] = dup2(b1R.y);
            Bs[0][knn + 8][(tx << 2) + 2] = dup2(b1R.z);
            Bs[0][knn + 8][(tx << 2) + 3] = dup2(b1R.w);
        }
    }
    __syncthreads();

    int s = 0;
    for (int k0 = 16;; k0 += 16) {
        const bool nxt = (k0 < K);
        if (nxt) {
            Aptr += 16;
            Bptr += BT ? 16 : 16 * N;
            aR  = *(const float4*)Aptr;
            b0R = *(const float4*)Bptr;
            b1R = BT ? *(const float4*)(Bptr + 32 * K)
                     : *(const float4*)(Bptr + 8 * N);
        }

#pragma unroll
        for (int kk = 0; kk < 16; kk++) {
            const ulonglong2 a2 = *(const ulonglong2*)&As[s][kk][ty << 2];
            const ulonglong2 bA = *(const ulonglong2*)&Bs[s][kk][tx << 2];
            const ulonglong2 bB = *(const ulonglong2*)&Bs[s][kk][(tx << 2) + 2];
            ffma2(acc[0][0], a2.x, bA.x);
            ffma2(acc[0][1], a2.x, bA.y);
            ffma2(acc[0][2], a2.x, bB.x);
            ffma2(acc[0][3], a2.x, bB.y);
            ffma2(acc[1][0], a2.y, bA.x);
            ffma2(acc[1][1], a2.y, bA.y);
            ffma2(acc[1][2], a2.y, bB.x);
            ffma2(acc[1][3], a2.y, bB.y);
        }

        if (!nxt) break;

        const int d = s ^ 1;
        As[d][lk + 0][lr] = aR.x;
        As[d][lk + 1][lr] = aR.y;
        As[d][lk + 2][lr] = aR.z;
        As[d][lk + 3][lr] = aR.w;
        if (BT) {
            Bs[d][lk + 0][lr] = dup2(b0R.x);
            Bs[d][lk + 1][lr] = dup2(b0R.y);
            Bs[d][lk + 2][lr] = dup2(b0R.z);
            Bs[d][lk + 3][lr] = dup2(b0R.w);
            Bs[d][lk + 0][lr + 32] = dup2(b1R.x);
            Bs[d][lk + 1][lr + 32] = dup2(b1R.y);
            Bs[d][lk + 2][lr + 32] = dup2(b1R.z);
            Bs[d][lk + 3][lr + 32] = dup2(b1R.w);
        } else {
            Bs[d][knn][(tx << 2) + 0] = dup2(b0R.x);
            Bs[d][knn][(tx << 2) + 1] = dup2(b0R.y);
            Bs[d][knn][(tx << 2) + 2] = dup2(b0R.z);
            Bs[d][knn][(tx << 2) + 3] = dup2(b0R.w);
            Bs[d][knn + 8][(tx << 2) + 0] = dup2(b1R.x);
            Bs[d][knn + 8][(tx << 2) + 1] = dup2(b1R.y);
            Bs[d][knn + 8][(tx << 2) + 2] = dup2(b1R.z);
            Bs[d][knn + 8][(tx << 2) + 3] = dup2(b1R.w);
        }
        __syncthreads();
        s = d;
    }

    float bv[4] = {0.f, 0.f, 0.f, 0.f};
    if (bias) {
        const float4 t = *(const float4*)&bias[n0 + (tx << 2)];
        bv[0] = t.x; bv[1] = t.y; bv[2] = t.z; bv[3] = t.w;
    }
#pragma unroll
    for (int p = 0; p < 2; p++) {
        const float2 f0 = unpk(acc[p][0]);
        const float2 f1 = unpk(acc[p][1]);
        const float2 f2 = unpk(acc[p][2]);
        const float2 f3 = unpk(acc[p][3]);
        const int r0 = m0 + (ty << 2) + (p << 1);
        float4 oa = make_float4(f0.x + bv[0], f1.x + bv[1], f2.x + bv[2], f3.x + bv[3]);
        float4 ob = make_float4(f0.y + bv[0], f1.y + bv[1], f2.y + bv[2], f3.y + bv[3]);
        if (RELU) {
            oa.x = fmaxf(oa.x, 0.f); oa.y = fmaxf(oa.y, 0.f);
            oa.z = fmaxf(oa.z, 0.f); oa.w = fmaxf(oa.w, 0.f);
            ob.x = fmaxf(ob.x, 0.f); ob.y = fmaxf(ob.y, 0.f);
            ob.z = fmaxf(ob.z, 0.f); ob.w = fmaxf(ob.w, 0.f);
        }
        *(float4*)&C[r0 * N + n0 + (tx << 2)]       = oa;
        *(float4*)&C[(r0 + 1) * N + n0 + (tx << 2)] = ob;
    }
}

template <bool BT, bool RELU>
__global__ void __launch_bounds__(128) gemm_k(
    const float* __restrict__ A, const float* __restrict__ Bm,
    const float* __restrict__ bias, float* __restrict__ C,
    int M, int N, int K)
{
    gemm_body<BT, RELU>(A, Bm, bias, C, M, N, K, blockIdx.x, blockIdx.y);
}

// ---------------------------------------------------------------------------
// Prologue: ALL weight/bias composes in one launch (132 blocks, one wave).
//   blocks   0..31  : Wqs  = Wq  @ Ws           (256x256)
//   blocks  32..95  : Wkvt = [Wk;Wv] @ Wt       (512x256)
//   blocks  96..127 : W1ao = W1 @ Wao           (256x256)
//   blocks 128..131 : composed biases
// ---------------------------------------------------------------------------
__global__ void __launch_bounds__(128) prologue_k(
    const float* __restrict__ Win, const float* __restrict__ bin,
    const float* __restrict__ Ws,  const float* __restrict__ bs,
    const float* __restrict__ Wt,  const float* __restrict__ bt,
    const float* __restrict__ W1,  const float* __restrict__ Wao,
    const float* __restrict__ bao, const float* __restrict__ b1)
{
    const int bid = blockIdx.x;
    if (bid < 32) {
        gemm_body<false, false>(Win, Ws, nullptr, g_Wqs, kH, kH, kH, bid & 3, bid >> 2);
    } else if (bid < 96) {
        const int t = bid - 32;
        gemm_body<false, false>(Win + kH * kH, Wt, nullptr, g_Wkvt,
                                2 * kH, kH, kH, t & 3, t >> 2);
    } else if (bid < 128) {
        const int t = bid - 96;
        gemm_body<false, false>(W1, Wao, nullptr, g_W1ao, kH, kH, kH, t & 3, t >> 2);
    } else {
        __shared__ float v[kH];
        const int i = threadIdx.x;          // 0..127, two outputs per thread
        const float* W;
        const float* badd;
        const float* vec;
        float* outp;
        if (bid == 128)      { vec = bs;  W = Win;               badd = bin;          outp = g_bqs;       }
        else if (bid == 129) { vec = bt;  W = Win + kH * kH;     badd = bin + kH;     outp = g_bkvt;      }
        else if (bid == 130) { vec = bt;  W = Win + 2 * kH * kH; badd = bin + 2 * kH; outp = g_bkvt + kH; }
        else                 { vec = bao; W = W1;                badd = b1;           outp = g_b1ao;      }
        v[i] = vec[i];
        v[i + 128] = vec[i + 128];
        __syncthreads();
#pragma unroll
        for (int r = 0; r < 2; r++) {
            const int o = i + r * 128;
            float a = 0.f;
#pragma unroll 8
            for (int m = 0; m < kH; m++) a += W[o * kH + m] * v[m];
            outp[o] = a + badd[o];
        }
    }
}

// ---------------------------------------------------------------------------
// q + kv projections in ONE launch (704 blocks):
//   blocks   0..511 : q  = spatial  @ Wqs^T  + bqs    (4096 x 256, K=256)
//   blocks 512..703 : kv = temporal @ Wkvt^T + bkvt   ( 768 x 512, K=256)
// ---------------------------------------------------------------------------
__global__ void __launch_bounds__(128) qkv_k(
    const float* __restrict__ spatial, const float* __restrict__ temporal)
{
    const int bid = blockIdx.x;
    if (bid < 512) {
        gemm_body<true, false>(spatial, g_Wqs, g_bqs, g_q, MQ, kH, kH,
                               bid & 3, bid >> 2);
    } else {
        const int t = bid - 512;   // 0..191
        gemm_body<true, false>(temporal, g_Wkvt, g_bkvt, g_kv, MT, 2 * kH, kH,
                               t & 7, t >> 3);
    }
}

// ---------------------------------------------------------------------------
// Fused attention: block = (n-tile of 128, head, batch), 128 threads.
// f32x2 packed math for QK dot and PV accumulate.
// ---------------------------------------------------------------------------
__global__ void __launch_bounds__(128) attn_k()
{
    const int b  = blockIdx.z;
    const int h  = blockIdx.y;
    const int n0 = blockIdx.x * 128;
    const int tid = threadIdx.x;

    __shared__ __align__(16) float ks[kS * kHD];
    __shared__ __align__(16) float vs[kS * kHD];

    for (int t = tid; t < kS * 8; t += 128) {
        const int s  = t >> 3;
        const int d4 = (t & 7) << 2;
        const float* row = &g_kv[(b * kS + s) * (2 * kH) + h * kHD];
        *(float4*)&ks[s * kHD + d4] = *(const float4*)&row[d4];
        *(float4*)&vs[s * kHD + d4] = *(const float4*)&row[kH + d4];
    }

    const int n = n0 + tid;
    const float* qrow = &g_q[(b * kN + n) * kH + h * kHD];
    constexpr float scale = 0.17677669529663687f;   // 1/sqrt(32)

    u64 q2[16];   // q pairs, pre-scaled
#pragma unroll
    for (int d4 = 0; d4 < 8; d4++) {
        const float4 t4 = *(const float4*)&qrow[d4 << 2];
        q2[(d4 << 1) + 0] = pack2(t4.x * scale, t4.y * scale);
        q2[(d4 << 1) + 1] = pack2(t4.z * scale, t4.w * scale);
    }
    __syncthreads();

    float m = -1e30f, l = 0.f;
    u64 acc2[16];
#pragma unroll
    for (int j = 0; j < 16; j++) acc2[j] = 0ull;

    for (int c = 0; c < kS / 16; c++) {       // 6 chunks of 16 keys
        float lg[16];
#pragma unroll
        for (int i = 0; i < 16; i++) {
            const float* kr = &ks[(c * 16 + i) * kHD];
            u64 d = 0ull;
#pragma unroll
            for (int d8 = 0; d8 < 8; d8++) {
                const ulonglong2 k2 = *(const ulonglong2*)&kr[d8 << 2];
                ffma2(d, q2[(d8 << 1) + 0], k2.x);
                ffma2(d, q2[(d8 << 1) + 1], k2.y);
            }
            const float2 f = unpk(d);
            lg[i] = f.x + f.y;
        }
        float cm = lg[0];
#pragma unroll
        for (int i = 1; i < 16; i++) cm = fmaxf(cm, lg[i]);
        const float nm   = fmaxf(m, cm);
        const float corr = __expf(m - nm);
        l *= corr;
        const u64 cd = dup2(corr);
#pragma unroll
        for (int j = 0; j < 16; j++) fmul2(acc2[j], cd);

#pragma unroll
        for (int i = 0; i < 16; i++) {
            const float p = __expf(lg[i] - nm);
            l += p;
            const u64 pd = dup2(p);
            const float* vr = &vs[(c * 16 + i) * kHD];
#pragma unroll
            for (int d8 = 0; d8 < 8; d8++) {
                const ulonglong2 v2 = *(const ulonglong2*)&vr[d8 << 2];
                ffma2(acc2[(d8 << 1) + 0], pd, v2.x);
                ffma2(acc2[(d8 << 1) + 1], pd, v2.y);
            }
        }
        m = nm;
    }

    const float inv = 1.f / l;
    float* orow = &g_ctx[(b * kN + n) * kH + h * kHD];
#pragma unroll
    for (int d4 = 0; d4 < 8; d4++) {
        const float2 f0 = unpk(acc2[(d4 << 1) + 0]);
        const float2 f1 = unpk(acc2[(d4 << 1) + 1]);
        *(float4*)&orow[d4 << 2] =
            make_float4(f0.x * inv, f0.y * inv, f1.x * inv, f1.y * inv);
    }
}

// ---------------------------------------------------------------------------
// h2 = relu(fused @ Wo1^T + bo1), y = h2 @ Wo2^T + bo2, broadcast to out.
// One CTA computes a full 32-row x 128-col h2 tile (so it owns complete h2
// rows), reduces to y in smem, and writes the (B,S,N,4) broadcast directly.
// 256 threads.
// ---------------------------------------------------------------------------
__global__ void __launch_bounds__(256) h2y_k(
    const float* __restrict__ Wo1, const float* __restrict__ bo1,
    const float* __restrict__ Wo2, const float* __restrict__ bo2,
    float4* __restrict__ out)
{
    __shared__ __align__(16) float As[2][16][32];
    __shared__ __align__(16) float Bsf[2][16][128];
    __shared__ __align__(16) float h2s[32][132];
    __shared__ float wT[128][4];
    __shared__ float4 ys[32];

    const int tid = threadIdx.x;       // 0..255
    const int m0  = blockIdx.x * 32;   // rows of g_fused / h2

    const int tx = tid & 31;           // col group: cols tx*4 .. +3 (128 cols)
    const int ty = tid >> 5;           // row group: rows ty*4 .. +3 (32 rows)

    if (tid < 128) {
#pragma unroll
        for (int o = 0; o < 4; o++) wT[tid][o] = Wo2[o * 128 + tid];
    }

    // loaders
    const int lrA = tid & 31;
    const int lkA = ((tid >> 5) & 3) << 2;      // tid<128: 0,4,8,12
    const int lrB = tid & 127;                  // n row 0..127
    const int lkB = (tid >> 7) << 3;            // 0 or 8

    const float* Aptr = g_fused + (m0 + lrA) * kH + lkA;
    const float* Bptr = Wo1 + lrB * kH + lkB;

    float4 aR = make_float4(0.f, 0.f, 0.f, 0.f);
    if (tid < 128) aR = *(const float4*)Aptr;
    float4 b0R = *(const float4*)Bptr;
    float4 b1R = *(const float4*)(Bptr + 4);

    u64 acc[2][4];
#pragma unroll
    for (int p = 0; p < 2; p++)
#pragma unroll
        for (int j = 0; j < 4; j++) acc[p][j] = 0ull;

    // stage 0
    if (tid < 128) {
        As[0][lkA + 0][lrA] = aR.x;
        As[0][lkA + 1][lrA] = aR.y;
        As[0][lkA + 2][lrA] = aR.z;
        As[0][lkA + 3][lrA] = aR.w;
    }
    Bsf[0][lkB + 0][lrB] = b0R.x;
    Bsf[0][lkB + 1][lrB] = b0R.y;
    Bsf[0][lkB + 2][lrB] = b0R.z;
    Bsf[0][lkB + 3][lrB] = b0R.w;
    Bsf[0][lkB + 4][lrB] = b1R.x;
    Bsf[0][lkB + 5][lrB] = b1R.y;
    Bsf[0][lkB + 6][lrB] = b1R.z;
    Bsf[0][lkB + 7][lrB] = b1R.w;
    __syncthreads();

    int s = 0;
    for (int k0 = 16;; k0 += 16) {
        const bool nxt = (k0 < kH);
        if (nxt) {
            Aptr += 16;
            Bptr += 16;
            if (tid < 128) aR = *(const float4*)Aptr;
            b0R = *(const float4*)Bptr;
            b1R = *(const float4*)(Bptr + 4);
        }

#pragma unroll
        for (int kk = 0; kk < 16; kk++) {
            const ulonglong2 a2 = *(const ulonglong2*)&As[s][kk][ty << 2];
            const float4 b4 = *(const float4*)&Bsf[s][kk][tx << 2];
            const u64 bd0 = dup2(b4.x);
            const u64 bd1 = dup2(b4.y);
            const u64 bd2 = dup2(b4.z);
            const u64 bd3 = dup2(b4.w);
            ffma2(acc[0][0], a2.x, bd0);
            ffma2(acc[0][1], a2.x, bd1);
            ffma2(acc[0][2], a2.x, bd2);
            ffma2(acc[0][3], a2.x, bd3);
            ffma2(acc[1][0], a2.y, bd0);
            ffma2(acc[1][1], a2.y, bd1);
            ffma2(acc[1][2], a2.y, bd2);
            ffma2(acc[1][3], a2.y, bd3);
        }

        if (!nxt) break;

        const int d = s ^ 1;
        if (tid < 128) {
            As[d][lkA + 0][lrA] = aR.x;
            As[d][lkA + 1][lrA] = aR.y;
            As[d][lkA + 2][lrA] = aR.z;
            As[d][lkA + 3][lrA] = aR.w;
        }
        Bsf[d][lkB + 0][lrB] = b0R.x;
        Bsf[d][lkB + 1][lrB] = b0R.y;
        Bsf[d][lkB + 2][lrB] = b0R.z;
        Bsf[d][lkB + 3][lrB] = b0R.w;
        Bsf[d][lkB + 4][lrB] = b1R.x;
        Bsf[d][lkB + 5][lrB] = b1R.y;
        Bsf[d][lkB + 6][lrB] = b1R.z;
        Bsf[d][lkB + 7][lrB] = b1R.w;
        __syncthreads();
        s = d;
    }

    // epilogue: bias + relu -> h2s
    {
        const float4 t = *(const float4*)&bo1[tx << 2];
#pragma unroll
        for (int p = 0; p < 2; p++) {
            const float2 f0 = unpk(acc[p][0]);
            const float2 f1 = unpk(acc[p][1]);
            const float2 f2 = unpk(acc[p][2]);
            const float2 f3 = unpk(acc[p][3]);
            const int r0 = (ty << 2) + (p << 1);
            *(float4*)&h2s[r0][tx << 2] = make_float4(
                fmaxf(f0.x + t.x, 0.f), fmaxf(f1.x + t.y, 0.f),
                fmaxf(f2.x + t.z, 0.f), fmaxf(f3.x + t.w, 0.f));
            *(float4*)&h2s[r0 + 1][tx << 2] = make_float4(
                fmaxf(f0.y + t.x, 0.f), fmaxf(f1.y + t.y, 0.f),
                fmaxf(f2.y + t.z, 0.f), fmaxf(f3.y + t.w, 0.f));
        }
    }
    __syncthreads();

    // y: one (row, out) pair per thread for tid < 128
    if (tid < 128) {
        const int row = tid >> 2;
        const int o   = tid & 3;
        float a = bo2[o];
#pragma unroll 16
        for (int i = 0; i < 128; i++) a += h2s[row][i] * wT[i][o];
        ((float*)ys)[(row << 2) + o] = a;
    }
    __syncthreads();

    // broadcast: out[b, s, n0+lane, :] = ys[lane] for all s
    const int bb    = m0 >> 9;          // batch
    const int nbase = m0 & (kN - 1);
    const int warp  = tid >> 5;
    const int lane  = tid & 31;
    const float4 yv = ys[lane];
#pragma unroll
    for (int sIdx = warp; sIdx < kS; sIdx += 8)
        out[(bb * kS + sIdx) * kN + nbase + lane] = yv;
}

// ---------------------------------------------------------------------------
// kernel_launch
// ---------------------------------------------------------------------------
extern "C" void kernel_launch(void* const* d_in, const int* in_sizes, int n_in,
                              void* d_out, int out_size)
{
    const float* spatial  = (const float*)d_in[0];
    const float* temporal = (const float*)d_in[1];
    const float* Ws  = (const float*)d_in[2];
    const float* bs  = (const float*)d_in[3];
    const float* Wt  = (const float*)d_in[4];
    const float* bt  = (const float*)d_in[5];
    const float* Win = (const float*)d_in[6];
    const float* bin = (const float*)d_in[7];
    const float* Wao = (const float*)d_in[8];
    const float* bao = (const float*)d_in[9];
    const float* W1  = (const float*)d_in[10];
    const float* b1  = (const float*)d_in[11];
    const float* Wo1 = (const float*)d_in[12];
    const float* bo1 = (const float*)d_in[13];
    const float* Wo2 = (const float*)d_in[14];
    const float* bo2 = (const float*)d_in[15];

    float *pW1ao, *pb1ao, *pctx, *pfused;
    cudaGetSymbolAddress((void**)&pW1ao,  g_W1ao);
    cudaGetSymbolAddress((void**)&pb1ao,  g_b1ao);
    cudaGetSymbolAddress((void**)&pctx,   g_ctx);
    cudaGetSymbolAddress((void**)&pfused, g_fused);

    // 1. all weight & bias composes (one wave)
    prologue_k<<<132, 128>>>(Win, bin, Ws, bs, Wt, bt, W1, Wao, bao, b1);

    // 2. q + kv projections (one launch, 704 blocks)
    qkv_k<<<704, 128>>>(spatial, temporal);

    // 3. attention -> ctx (4096 x 256)
    attn_k<<<dim3(kN / 128, kNH, kB), 128>>>();

    // 4. fused = relu(ctx @ W1ao^T + b1ao)   (4096 x 256)
    gemm_k<true, true><<<dim3(kH / 64, MQ / 32), 128>>>(pctx, pW1ao, pb1ao, pfused,
                                                        MQ, kH, kH);

    // 5. h2 + y + broadcast (128 CTAs, 256 threads)
    h2y_k<<<MQ / 32, 256>>>(Wo1, bo1, Wo2, bo2, (float4*)d_out);
}

// round 12
// speedup vs baseline: 1.5063x; 1.5063x over previous
#include <cuda_runtime.h>

// ---------------------------------------------------------------------------
// Problem constants
// ---------------------------------------------------------------------------
namespace {
constexpr int kB  = 8;
constexpr int kN  = 512;
constexpr int kS  = 96;
constexpr int kH  = 256;
constexpr int kNH = 8;
constexpr int kHD = 32;
constexpr int kOUT = 4;
constexpr int MQ = kB * kN;   // 4096 query rows
constexpr int MT = kB * kS;   // 768 temporal rows
}

// ---------------------------------------------------------------------------
// Scratch (device globals — no allocation allowed)
// ---------------------------------------------------------------------------
__device__ __align__(16) float g_Wqs[kH * kH];        // Wq @ Ws
__device__ __align__(16) float g_Wkvt[2 * kH * kH];   // [Wk;Wv] @ Wt
__device__ __align__(16) float g_W1ao[kH * kH];       // W1 @ Wao
__device__ __align__(16) float g_bqs[kH];
__device__ __align__(16) float g_bkvt[2 * kH];
__device__ __align__(16) float g_b1ao[kH];
__device__ __align__(16) float g_q[MQ * kH];
__device__ __align__(16) float g_kv[MT * 2 * kH];     // [..,0:256]=k, [..,256:512]=v
__device__ __align__(16) float g_ctx[MQ * kH];
__device__ __align__(16) float g_fused[MQ * kH];

// ---------------------------------------------------------------------------
// f32x2 packed-math helpers (sm_103a fma.rn.f32x2 — PTX only)
// ---------------------------------------------------------------------------
using u64 = unsigned long long;
__device__ __forceinline__ u64 pack2(float lo, float hi) {
    u64 r; asm("mov.b64 %0, {%1, %2};" : "=l"(r) : "f"(lo), "f"(hi)); return r;
}
__device__ __forceinline__ u64 dup2(float x) {
    u64 r; asm("mov.b64 %0, {%1, %1};" : "=l"(r) : "f"(x)); return r;
}
__device__ __forceinline__ void ffma2(u64& d, u64 a, u64 b) {
    asm("fma.rn.f32x2 %0, %1, %2, %0;" : "+l"(d) : "l"(a), "l"(b));
}
__device__ __forceinline__ void fmul2(u64& d, u64 a) {
    asm("mul.rn.f32x2 %0, %0, %1;" : "+l"(d) : "l"(a));
}
__device__ __forceinline__ float2 unpk(u64 v) {
    float2 f; asm("mov.b64 {%0, %1}, %2;" : "=f"(f.x), "=f"(f.y) : "l"(v)); return f;
}

// ---------------------------------------------------------------------------
// FFMA2 SGEMM body: C[M,N] = A[M,K] @ op(B) + bias, optional ReLU
//   BT = true :  op(B) = B^T, B row-major [N,K]   (NT)
//   BT = false:  op(B) = B,   B row-major [K,N]   (NN)
// 64x64 block tile, BK=16, 128 threads, 8x4 per thread.
// Smem layout identical to the round-8 float version (48 B LDS per 32 MACs);
// the MACs run as 16 fma.rn.f32x2 with B duplicated IN REGISTERS (4 movs),
// accumulators paired along M (pairs come free from ulonglong2 A reads).
// Requires M%64==0, N%64==0, K%16==0, K>=32.
// ---------------------------------------------------------------------------
template <bool BT, bool RELU>
__device__ __forceinline__ void gemm_body(
    const float* __restrict__ A, const float* __restrict__ Bm,
    const float* __restrict__ bias, float* __restrict__ C,
    int M, int N, int K, int bx, int by)
{
    __shared__ __align__(16) float As[2][16][64];
    __shared__ __align__(16) float Bs[2][16][64];

    const int tid = threadIdx.x;       // 0..127
    const int tx  = tid & 15;          // col group: cols n0 + tx*4 .. +3
    const int ty  = tid >> 4;          // row group: rows m0 + ty*8 .. +7
    const int m0  = by * 64;
    const int n0  = bx * 64;

    // Loader mapping: lane = row (conflict-free scalar STS), warp = k-quarter.
    const int lr = tid & 31;           // row within half-tile (0..31)
    const int lk = (tid >> 5) << 2;    // k offset: 0,4,8,12
    const int bKnn = tid >> 4;         // 0..7   (NN)
    const int bNnn = (tid & 15) << 2;  // 0..60  (NN)

    const float* Aptr = A + (m0 + lr) * K + lk;
    const float* Bptr = BT ? (Bm + (n0 + lr) * K + lk)
                           : (Bm + bKnn * N + n0 + bNnn);

    float4 a0R = *(const float4*)Aptr;
    float4 a1R = *(const float4*)(Aptr + 32 * K);
    float4 b0R = *(const float4*)Bptr;
    float4 b1R = BT ? *(const float4*)(Bptr + 32 * K)
                    : *(const float4*)(Bptr + 8 * N);

    u64 acc[4][4];   // [m-pair][n]
#pragma unroll
    for (int p = 0; p < 4; p++)
#pragma unroll
        for (int j = 0; j < 4; j++) acc[p][j] = 0ull;

    // stage 0 store
    {
        As[0][lk + 0][lr] = a0R.x;
        As[0][lk + 1][lr] = a0R.y;
        As[0][lk + 2][lr] = a0R.z;
        As[0][lk + 3][lr] = a0R.w;
        As[0][lk + 0][lr + 32] = a1R.x;
        As[0][lk + 1][lr + 32] = a1R.y;
        As[0][lk + 2][lr + 32] = a1R.z;
        As[0][lk + 3][lr + 32] = a1R.w;
        if (BT) {
            Bs[0][lk + 0][lr] = b0R.x;
            Bs[0][lk + 1][lr] = b0R.y;
            Bs[0][lk + 2][lr] = b0R.z;
            Bs[0][lk + 3][lr] = b0R.w;
            Bs[0][lk + 0][lr + 32] = b1R.x;
            Bs[0][lk + 1][lr + 32] = b1R.y;
            Bs[0][lk + 2][lr + 32] = b1R.z;
            Bs[0][lk + 3][lr + 32] = b1R.w;
        } else {
            *(float4*)&Bs[0][bKnn][bNnn] = b0R;
            *(float4*)&Bs[0][bKnn + 8][bNnn] = b1R;
        }
    }
    __syncthreads();

    int s = 0;
    for (int k0 = 16;; k0 += 16) {
        const bool nxt = (k0 < K);
        if (nxt) {
            Aptr += 16;
            Bptr += BT ? 16 : 16 * N;
            a0R = *(const float4*)Aptr;
            a1R = *(const float4*)(Aptr + 32 * K);
            b0R = *(const float4*)Bptr;
            b1R = BT ? *(const float4*)(Bptr + 32 * K)
                     : *(const float4*)(Bptr + 8 * N);
        }

#pragma unroll
        for (int kk = 0; kk < 16; kk++) {
            const ulonglong2 aLo = *(const ulonglong2*)&As[s][kk][ty << 3];
            const ulonglong2 aHi = *(const ulonglong2*)&As[s][kk][(ty << 3) + 4];
            const float4 b4 = *(const float4*)&Bs[s][kk][tx << 2];
            const u64 bd0 = dup2(b4.x);
            const u64 bd1 = dup2(b4.y);
            const u64 bd2 = dup2(b4.z);
            const u64 bd3 = dup2(b4.w);
            ffma2(acc[0][0], aLo.x, bd0);
            ffma2(acc[0][1], aLo.x, bd1);
            ffma2(acc[0][2], aLo.x, bd2);
            ffma2(acc[0][3], aLo.x, bd3);
            ffma2(acc[1][0], aLo.y, bd0);
            ffma2(acc[1][1], aLo.y, bd1);
            ffma2(acc[1][2], aLo.y, bd2);
            ffma2(acc[1][3], aLo.y, bd3);
            ffma2(acc[2][0], aHi.x, bd0);
            ffma2(acc[2][1], aHi.x, bd1);
            ffma2(acc[2][2], aHi.x, bd2);
            ffma2(acc[2][3], aHi.x, bd3);
            ffma2(acc[3][0], aHi.y, bd0);
            ffma2(acc[3][1], aHi.y, bd1);
            ffma2(acc[3][2], aHi.y, bd2);
            ffma2(acc[3][3], aHi.y, bd3);
        }

        if (!nxt) break;

        const int d = s ^ 1;
        As[d][lk + 0][lr] = a0R.x;
        As[d][lk + 1][lr] = a0R.y;
        As[d][lk + 2][lr] = a0R.z;
        As[d][lk + 3][lr] = a0R.w;
        As[d][lk + 0][lr + 32] = a1R.x;
        As[d][lk + 1][lr + 32] = a1R.y;
        As[d][lk + 2][lr + 32] = a1R.z;
        As[d][lk + 3][lr + 32] = a1R.w;
        if (BT) {
            Bs[d][lk + 0][lr] = b0R.x;
            Bs[d][lk + 1][lr] = b0R.y;
            Bs[d][lk + 2][lr] = b0R.z;
            Bs[d][lk + 3][lr] = b0R.w;
            Bs[d][lk + 0][lr + 32] = b1R.x;
            Bs[d][lk + 1][lr + 32] = b1R.y;
            Bs[d][lk + 2][lr + 32] = b1R.z;
            Bs[d][lk + 3][lr + 32] = b1R.w;
        } else {
            *(float4*)&Bs[d][bKnn][bNnn] = b0R;
            *(float4*)&Bs[d][bKnn + 8][bNnn] = b1R;
        }
        __syncthreads();
        s = d;
    }

    float bv[4] = {0.f, 0.f, 0.f, 0.f};
    if (bias) {
        const float4 t = *(const float4*)&bias[n0 + (tx << 2)];
        bv[0] = t.x; bv[1] = t.y; bv[2] = t.z; bv[3] = t.w;
    }
#pragma unroll
    for (int p = 0; p < 4; p++) {
        const float2 f0 = unpk(acc[p][0]);
        const float2 f1 = unpk(acc[p][1]);
        const float2 f2 = unpk(acc[p][2]);
        const float2 f3 = unpk(acc[p][3]);
        const int r0 = m0 + (ty << 3) + (p << 1);
        float4 oa = make_float4(f0.x + bv[0], f1.x + bv[1], f2.x + bv[2], f3.x + bv[3]);
        float4 ob = make_float4(f0.y + bv[0], f1.y + bv[1], f2.y + bv[2], f3.y + bv[3]);
        if (RELU) {
            oa.x = fmaxf(oa.x, 0.f); oa.y = fmaxf(oa.y, 0.f);
            oa.z = fmaxf(oa.z, 0.f); oa.w = fmaxf(oa.w, 0.f);
            ob.x = fmaxf(ob.x, 0.f); ob.y = fmaxf(ob.y, 0.f);
            ob.z = fmaxf(ob.z, 0.f); ob.w = fmaxf(ob.w, 0.f);
        }
        *(float4*)&C[r0 * N + n0 + (tx << 2)]       = oa;
        *(float4*)&C[(r0 + 1) * N + n0 + (tx << 2)] = ob;
    }
}

template <bool BT, bool RELU>
__global__ void __launch_bounds__(128) gemm_k(
    const float* __restrict__ A, const float* __restrict__ Bm,
    const float* __restrict__ bias, float* __restrict__ C,
    int M, int N, int K)
{
    gemm_body<BT, RELU>(A, Bm, bias, C, M, N, K, blockIdx.x, blockIdx.y);
}

// ---------------------------------------------------------------------------
// Prologue: ALL weight/bias composes in one launch (68 blocks, one wave).
//   blocks  0..15 : Wqs  = Wq  @ Ws           (256x256)
//   blocks 16..47 : Wkvt = [Wk;Wv] @ Wt       (512x256)
//   blocks 48..63 : W1ao = W1 @ Wao           (256x256)
//   blocks 64..67 : composed biases
// ---------------------------------------------------------------------------
__global__ void __launch_bounds__(128) prologue_k(
    const float* __restrict__ Win, const float* __restrict__ bin,
    const float* __restrict__ Ws,  const float* __restrict__ bs,
    const float* __restrict__ Wt,  const float* __restrict__ bt,
    const float* __restrict__ W1,  const float* __restrict__ Wao,
    const float* __restrict__ bao, const float* __restrict__ b1)
{
    const int bid = blockIdx.x;
    if (bid < 16) {
        gemm_body<false, false>(Win, Ws, nullptr, g_Wqs, kH, kH, kH, bid & 3, bid >> 2);
    } else if (bid < 48) {
        const int t = bid - 16;
        gemm_body<false, false>(Win + kH * kH, Wt, nullptr, g_Wkvt,
                                2 * kH, kH, kH, t & 3, t >> 2);
    } else if (bid < 64) {
        const int t = bid - 48;
        gemm_body<false, false>(W1, Wao, nullptr, g_W1ao, kH, kH, kH, t & 3, t >> 2);
    } else {
        __shared__ float v[kH];
        const int i = threadIdx.x;          // 0..127, two outputs per thread
        const float* W;
        const float* badd;
        const float* vec;
        float* outp;
        if (bid == 64)      { vec = bs;  W = Win;               badd = bin;          outp = g_bqs;       }
        else if (bid == 65) { vec = bt;  W = Win + kH * kH;     badd = bin + kH;     outp = g_bkvt;      }
        else if (bid == 66) { vec = bt;  W = Win + 2 * kH * kH; badd = bin + 2 * kH; outp = g_bkvt + kH; }
        else                 { vec = bao; W = W1;               badd = b1;           outp = g_b1ao;      }
        v[i] = vec[i];
        v[i + 128] = vec[i + 128];
        __syncthreads();
#pragma unroll
        for (int r = 0; r < 2; r++) {
            const int o = i + r * 128;
            float a = 0.f;
#pragma unroll 8
            for (int m = 0; m < kH; m++) a += W[o * kH + m] * v[m];
            outp[o] = a + badd[o];
        }
    }
}

// ---------------------------------------------------------------------------
// q + kv projections in ONE launch (352 blocks):
//   blocks   0..255 : q  = spatial  @ Wqs^T  + bqs    (4096 x 256, K=256)
//   blocks 256..351 : kv = temporal @ Wkvt^T + bkvt   ( 768 x 512, K=256)
// ---------------------------------------------------------------------------
__global__ void __launch_bounds__(128) qkv_k(
    const float* __restrict__ spatial, const float* __restrict__ temporal)
{
    const int bid = blockIdx.x;
    if (bid < 256) {
        gemm_body<true, false>(spatial, g_Wqs, g_bqs, g_q, MQ, kH, kH,
                               bid & 3, bid >> 2);
    } else {
        const int t = bid - 256;   // 0..95
        gemm_body<true, false>(temporal, g_Wkvt, g_bkvt, g_kv, MT, 2 * kH, kH,
                               t & 7, t >> 3);
    }
}

// ---------------------------------------------------------------------------
// Fused attention: block = (n-tile of 128, head, batch), 128 threads.
// f32x2 packed math for QK dot and PV accumulate (smem reads are broadcasts).
// ---------------------------------------------------------------------------
__global__ void __launch_bounds__(128) attn_k()
{
    const int b  = blockIdx.z;
    const int h  = blockIdx.y;
    const int n0 = blockIdx.x * 128;
    const int tid = threadIdx.x;

    __shared__ __align__(16) float ks[kS * kHD];
    __shared__ __align__(16) float vs[kS * kHD];

    for (int t = tid; t < kS * 8; t += 128) {
        const int s  = t >> 3;
        const int d4 = (t & 7) << 2;
        const float* row = &g_kv[(b * kS + s) * (2 * kH) + h * kHD];
        *(float4*)&ks[s * kHD + d4] = *(const float4*)&row[d4];
        *(float4*)&vs[s * kHD + d4] = *(const float4*)&row[kH + d4];
    }

    const int n = n0 + tid;
    const float* qrow = &g_q[(b * kN + n) * kH + h * kHD];
    constexpr float scale = 0.17677669529663687f;   // 1/sqrt(32)

    u64 q2[16];   // q pairs, pre-scaled
#pragma unroll
    for (int d4 = 0; d4 < 8; d4++) {
        const float4 t4 = *(const float4*)&qrow[d4 << 2];
        q2[(d4 << 1) + 0] = pack2(t4.x * scale, t4.y * scale);
        q2[(d4 << 1) + 1] = pack2(t4.z * scale, t4.w * scale);
    }
    __syncthreads();

    float m = -1e30f, l = 0.f;
    u64 acc2[16];
#pragma unroll
    for (int j = 0; j < 16; j++) acc2[j] = 0ull;

    for (int c = 0; c < kS / 16; c++) {       // 6 chunks of 16 keys
        float lg[16];
#pragma unroll
        for (int i = 0; i < 16; i++) {
            const float* kr = &ks[(c * 16 + i) * kHD];
            u64 d = 0ull;
#pragma unroll
            for (int d8 = 0; d8 < 8; d8++) {
                const ulonglong2 k2 = *(const ulonglong2*)&kr[d8 << 2];
                ffma2(d, q2[(d8 << 1) + 0], k2.x);
                ffma2(d, q2[(d8 << 1) + 1], k2.y);
            }
            const float2 f = unpk(d);
            lg[i] = f.x + f.y;
        }
        float cm = lg[0];
#pragma unroll
        for (int i = 1; i < 16; i++) cm = fmaxf(cm, lg[i]);
        const float nm   = fmaxf(m, cm);
        const float corr = __expf(m - nm);
        l *= corr;
        const u64 cd = dup2(corr);
#pragma unroll
        for (int j = 0; j < 16; j++) fmul2(acc2[j], cd);

#pragma unroll
        for (int i = 0; i < 16; i++) {
            const float p = __expf(lg[i] - nm);
            l += p;
            const u64 pd = dup2(p);
            const float* vr = &vs[(c * 16 + i) * kHD];
#pragma unroll
            for (int d8 = 0; d8 < 8; d8++) {
                const ulonglong2 v2 = *(const ulonglong2*)&vr[d8 << 2];
                ffma2(acc2[(d8 << 1) + 0], pd, v2.x);
                ffma2(acc2[(d8 << 1) + 1], pd, v2.y);
            }
        }
        m = nm;
    }

    const float inv = 1.f / l;
    float* orow = &g_ctx[(b * kN + n) * kH + h * kHD];
#pragma unroll
    for (int d4 = 0; d4 < 8; d4++) {
        const float2 f0 = unpk(acc2[(d4 << 1) + 0]);
        const float2 f1 = unpk(acc2[(d4 << 1) + 1]);
        *(float4*)&orow[d4 << 2] =
            make_float4(f0.x * inv, f0.y * inv, f1.x * inv, f1.y * inv);
    }
}

// ---------------------------------------------------------------------------
// h2 = relu(fused @ Wo1^T + bo1), y = h2 @ Wo2^T + bo2, broadcast to out.
// One CTA computes a full 32-row x 128-col h2 tile (so it owns complete h2
// rows), reduces to y in smem, and writes the (B,S,N,4) broadcast directly.
// 256 threads; B duplicated in registers at use.
// ---------------------------------------------------------------------------
__global__ void __launch_bounds__(256) h2y_k(
    const float* __restrict__ Wo1, const float* __restrict__ bo1,
    const float* __restrict__ Wo2, const float* __restrict__ bo2,
    float4* __restrict__ out)
{
    __shared__ __align__(16) float As[2][16][32];
    __shared__ __align__(16) float Bsf[2][16][128];
    __shared__ __align__(16) float h2s[32][132];
    __shared__ float wT[128][4];
    __shared__ float4 ys[32];

    const int tid = threadIdx.x;       // 0..255
    const int m0  = blockIdx.x * 32;   // rows of g_fused / h2

    const int tx = tid & 31;           // col group: cols tx*4 .. +3 (128 cols)
    const int ty = tid >> 5;           // row group: rows ty*4 .. +3 (32 rows)

    if (tid < 128) {
#pragma unroll
        for (int o = 0; o < 4; o++) wT[tid][o] = Wo2[o * 128 + tid];
    }

    // loaders
    const int lrA = tid & 31;
    const int lkA = ((tid >> 5) & 3) << 2;      // tid<128: 0,4,8,12
    const int lrB = tid & 127;                  // n row 0..127
    const int lkB = (tid >> 7) << 3;            // 0 or 8

    const float* Aptr = g_fused + (m0 + lrA) * kH + lkA;
    const float* Bptr = Wo1 + lrB * kH + lkB;

    float4 aR = make_float4(0.f, 0.f, 0.f, 0.f);
    if (tid < 128) aR = *(const float4*)Aptr;
    float4 b0R = *(const float4*)Bptr;
    float4 b1R = *(const float4*)(Bptr + 4);

    u64 acc[2][4];
#pragma unroll
    for (int p = 0; p < 2; p++)
#pragma unroll
        for (int j = 0; j < 4; j++) acc[p][j] = 0ull;

    // stage 0
    if (tid < 128) {
        As[0][lkA + 0][lrA] = aR.x;
        As[0][lkA + 1][lrA] = aR.y;
        As[0][lkA + 2][lrA] = aR.z;
        As[0][lkA + 3][lrA] = aR.w;
    }
    Bsf[0][lkB + 0][lrB] = b0R.x;
    Bsf[0][lkB + 1][lrB] = b0R.y;
    Bsf[0][lkB + 2][lrB] = b0R.z;
    Bsf[0][lkB + 3][lrB] = b0R.w;
    Bsf[0][lkB + 4][lrB] = b1R.x;
    Bsf[0][lkB + 5][lrB] = b1R.y;
    Bsf[0][lkB + 6][lrB] = b1R.z;
    Bsf[0][lkB + 7][lrB] = b1R.w;
    __syncthreads();

    int s = 0;
    for (int k0 = 16;; k0 += 16) {
        const bool nxt = (k0 < kH);
        if (nxt) {
            Aptr += 16;
            Bptr += 16;
            if (tid < 128) aR = *(const float4*)Aptr;
            b0R = *(const float4*)Bptr;
            b1R = *(const float4*)(Bptr + 4);
        }

#pragma unroll
        for (int kk = 0; kk < 16; kk++) {
            const ulonglong2 a2 = *(const ulonglong2*)&As[s][kk][ty << 2];
            const float4 b4 = *(const float4*)&Bsf[s][kk][tx << 2];
            const u64 bd0 = dup2(b4.x);
            const u64 bd1 = dup2(b4.y);
            const u64 bd2 = dup2(b4.z);
            const u64 bd3 = dup2(b4.w);
            ffma2(acc[0][0], a2.x, bd0);
            ffma2(acc[0][1], a2.x, bd1);
            ffma2(acc[0][2], a2.x, bd2);
            ffma2(acc[0][3], a2.x, bd3);
            ffma2(acc[1][0], a2.y, bd0);
            ffma2(acc[1][1], a2.y, bd1);
            ffma2(acc[1][2], a2.y, bd2);
            ffma2(acc[1][3], a2.y, bd3);
        }

        if (!nxt) break;

        const int d = s ^ 1;
        if (tid < 128) {
            As[d][lkA + 0][lrA] = aR.x;
            As[d][lkA + 1][lrA] = aR.y;
            As[d][lkA + 2][lrA] = aR.z;
            As[d][lkA + 3][lrA] = aR.w;
        }
        Bsf[d][lkB + 0][lrB] = b0R.x;
        Bsf[d][lkB + 1][lrB] = b0R.y;
        Bsf[d][lkB + 2][lrB] = b0R.z;
        Bsf[d][lkB + 3][lrB] = b0R.w;
        Bsf[d][lkB + 4][lrB] = b1R.x;
        Bsf[d][lkB + 5][lrB] = b1R.y;
        Bsf[d][lkB + 6][lrB] = b1R.z;
        Bsf[d][lkB + 7][lrB] = b1R.w;
        __syncthreads();
        s = d;
    }

    // epilogue: bias + relu -> h2s
    {
        const float4 t = *(const float4*)&bo1[tx << 2];
#pragma unroll
        for (int p = 0; p < 2; p++) {
            const float2 f0 = unpk(acc[p][0]);
            const float2 f1 = unpk(acc[p][1]);
            const float2 f2 = unpk(acc[p][2]);
            const float2 f3 = unpk(acc[p][3]);
            const int r0 = (ty << 2) + (p << 1);
            *(float4*)&h2s[r0][tx << 2] = make_float4(
                fmaxf(f0.x + t.x, 0.f), fmaxf(f1.x + t.y, 0.f),
                fmaxf(f2.x + t.z, 0.f), fmaxf(f3.x + t.w, 0.f));
            *(float4*)&h2s[r0 + 1][tx << 2] = make_float4(
                fmaxf(f0.y + t.x, 0.f), fmaxf(f1.y + t.y, 0.f),
                fmaxf(f2.y + t.z, 0.f), fmaxf(f3.y + t.w, 0.f));
        }
    }
    __syncthreads();

    // y: one (row, out) pair per thread for tid < 128
    if (tid < 128) {
        const int row = tid >> 2;
        const int o   = tid & 3;
        float a = bo2[o];
#pragma unroll 16
        for (int i = 0; i < 128; i++) a += h2s[row][i] * wT[i][o];
        ((float*)ys)[(row << 2) + o] = a;
    }
    __syncthreads();

    // broadcast: out[b, s, n0+lane, :] = ys[lane] for all s
    const int bb    = m0 >> 9;          // batch
    const int nbase = m0 & (kN - 1);
    const int warp  = tid >> 5;
    const int lane  = tid & 31;
    const float4 yv = ys[lane];
#pragma unroll
    for (int sIdx = warp; sIdx < kS; sIdx += 8)
        out[(bb * kS + sIdx) * kN + nbase + lane] = yv;
}

// ---------------------------------------------------------------------------
// kernel_launch
// ---------------------------------------------------------------------------
extern "C" void kernel_launch(void* const* d_in, const int* in_sizes, int n_in,
                              void* d_out, int out_size)
{
    const float* spatial  = (const float*)d_in[0];
    const float* temporal = (const float*)d_in[1];
    const float* Ws  = (const float*)d_in[2];
    const float* bs  = (const float*)d_in[3];
    const float* Wt  = (const float*)d_in[4];
    const float* bt  = (const float*)d_in[5];
    const float* Win = (const float*)d_in[6];
    const float* bin = (const float*)d_in[7];
    const float* Wao = (const float*)d_in[8];
    const float* bao = (const float*)d_in[9];
    const float* W1  = (const float*)d_in[10];
    const float* b1  = (const float*)d_in[11];
    const float* Wo1 = (const float*)d_in[12];
    const float* bo1 = (const float*)d_in[13];
    const float* Wo2 = (const float*)d_in[14];
    const float* bo2 = (const float*)d_in[15];

    float *pW1ao, *pb1ao, *pctx, *pfused;
    cudaGetSymbolAddress((void**)&pW1ao,  g_W1ao);
    cudaGetSymbolAddress((void**)&pb1ao,  g_b1ao);
    cudaGetSymbolAddress((void**)&pctx,   g_ctx);
    cudaGetSymbolAddress((void**)&pfused, g_fused);

    // 1. all weight & bias composes (one wave)
    prologue_k<<<68, 128>>>(Win, bin, Ws, bs, Wt, bt, W1, Wao, bao, b1);

    // 2. q + kv projections (one launch, 352 blocks)
    qkv_k<<<352, 128>>>(spatial, temporal);

    // 3. attention -> ctx (4096 x 256)
    attn_k<<<dim3(kN / 128, kNH, kB), 128>>>();

    // 4. fused = relu(ctx @ W1ao^T + b1ao)   (4096 x 256)
    gemm_k<true, true><<<dim3(kH / 64, MQ / 64), 128>>>(pctx, pW1ao, pb1ao, pfused,
                                                        MQ, kH, kH);

    // 5. h2 + y + broadcast (128 CTAs, 256 threads)
    h2y_k<<<MQ / 32, 256>>>(Wo1, bo1, Wo2, bo2, (float4*)d_out);
}